// round 17
// baseline (speedup 1.0000x reference)
#include <cuda_runtime.h>
#include <cuda_fp16.h>
#include <math.h>
#include <cstdint>

#define BB   4
#define SS   2048
#define DIMC 2048
#define NH   16
#define NKV  4
#define HD   128
#define QKVC 3072
#define EPSF 1.1920928955078125e-07f
#define NEGF -1e30f

// Scratch (device globals: allocation-free per harness rules)
__device__ __half g_qkvh[(size_t)BB * SS * QKVC];   // fp16, COMPACTED rows
__device__ __half g_attnh[(size_t)BB * SS * DIMC];  // fp16, COMPACTED rows
__device__ __half g_xh[(size_t)BB * SS * DIMC];
__device__ __half g_wqh[(size_t)QKVC * DIMC];
__device__ __half g_woh[(size_t)DIMC * DIMC];
__device__ unsigned char g_mask[BB * SS];
__device__ int g_vidx[BB * SS];                     // compacted visible token idx
__device__ int g_nvis[BB];                          // visible count per batch

// ===========================================================================
// Portable helpers (sm_80-baseline ISA; no 'a'-suffix features)
// ===========================================================================
__device__ __forceinline__ uint32_t smem_u32(const void* p) {
    uint32_t a;
    asm("{ .reg .u64 t; cvta.to.shared.u64 t, %1; cvt.u32.u64 %0, t; }" : "=r"(a) : "l"(p));
    return a;
}
__device__ __forceinline__ void cp16(uint32_t s, const void* g) {
    asm volatile("cp.async.cg.shared.global [%0], [%1], 16;" :: "r"(s), "l"(g));
}
#define CP_COMMIT() asm volatile("cp.async.commit_group;" ::: "memory")
#define CP_WAIT(n)  asm volatile("cp.async.wait_group %0;" :: "n"(n) : "memory")

__device__ __forceinline__ void ldsm4(uint32_t* r, uint32_t a) {
    asm volatile("ldmatrix.sync.aligned.m8n8.x4.shared.b16 {%0,%1,%2,%3}, [%4];"
                 : "=r"(r[0]), "=r"(r[1]), "=r"(r[2]), "=r"(r[3]) : "r"(a));
}
__device__ __forceinline__ void ldsm4t(uint32_t* r, uint32_t a) {
    asm volatile("ldmatrix.sync.aligned.m8n8.x4.trans.shared.b16 {%0,%1,%2,%3}, [%4];"
                 : "=r"(r[0]), "=r"(r[1]), "=r"(r[2]), "=r"(r[3]) : "r"(a));
}
__device__ __forceinline__ void mma_f16(float* c, uint32_t a0, uint32_t a1,
                                        uint32_t a2, uint32_t a3,
                                        uint32_t b0, uint32_t b1) {
    asm volatile(
        "mma.sync.aligned.m16n8k16.row.col.f32.f16.f16.f32 "
        "{%0,%1,%2,%3}, {%4,%5,%6,%7}, {%8,%9}, {%0,%1,%2,%3};"
        : "+f"(c[0]), "+f"(c[1]), "+f"(c[2]), "+f"(c[3])
        : "r"(a0), "r"(a1), "r"(a2), "r"(a3), "r"(b0), "r"(b1));
}

// ===========================================================================
// Fused prep 1: mask canonicalization + per-batch visible compaction.
// ===========================================================================
__global__ __launch_bounds__(1024) void prep_mask(const unsigned char* __restrict__ raw)
{
    __shared__ int kind;  // 0=int32, 1=bool/u8, 2=float32
    __shared__ int sa[1024], sb[1024];
    const int b = blockIdx.x, t = threadIdx.x;

    if (t == 0) kind = 0;
    __syncthreads();
    for (int i = t; i < BB * SS; i += 1024) {
        unsigned char v = raw[i];
        if ((i & 3) == 3 && v == 0x3F) kind = 2;
        else if ((i & 3) != 0 && v != 0) kind = 1;
    }
    __syncthreads();
    const int k = kind;

    int m0, m1;
    {
        const int i0 = b * SS + 2 * t, i1 = i0 + 1;
        if (k == 2)      { m0 = (((const float*)raw)[i0] != 0.0f); m1 = (((const float*)raw)[i1] != 0.0f); }
        else if (k == 1) { m0 = (raw[i0] != 0); m1 = (raw[i1] != 0); }
        else             { m0 = (((const int*)raw)[i0] != 0); m1 = (((const int*)raw)[i1] != 0); }
        g_mask[i0] = (unsigned char)m0;
        g_mask[i1] = (unsigned char)m1;
    }

    sa[t] = m0 + m1;
    __syncthreads();
    int* src = sa;
    int* dst = sb;
    for (int off = 1; off < 1024; off <<= 1) {
        dst[t] = src[t] + ((t >= off) ? src[t - off] : 0);
        __syncthreads();
        int* tmp = src; src = dst; dst = tmp;
    }
    const int incl = src[t];
    int ex = incl - (m0 + m1);
    if (m0) g_vidx[b * SS + ex] = 2 * t, ex++;
    if (m1) g_vidx[b * SS + ex] = 2 * t + 1;
    if (t == 1023) g_nvis[b] = incl;
}

// ===========================================================================
// Fused prep 2: fp32->fp16 of x, wqkv, wo in one grid-stride kernel.
// ===========================================================================
#define N2_X  (BB * SS * DIMC / 2)
#define N2_WQ (QKVC * DIMC / 2)
#define N2_WO (DIMC * DIMC / 2)
__global__ __launch_bounds__(256) void cvt_all(const float2* __restrict__ x,
                                               const float2* __restrict__ wq,
                                               const float2* __restrict__ wo,
                                               __half2* __restrict__ xh,
                                               __half2* __restrict__ wqh,
                                               __half2* __restrict__ woh)
{
    const int total = N2_X + N2_WQ + N2_WO;
    for (int i = blockIdx.x * 256 + threadIdx.x; i < total; i += gridDim.x * 256) {
        float2 v;
        __half2* o;
        int j;
        if (i < N2_X)                { j = i; v = x[j]; o = xh + j; }
        else if (i < N2_X + N2_WQ)   { j = i - N2_X; v = wq[j]; o = wqh + j; }
        else                         { j = i - N2_X - N2_WQ; v = wo[j]; o = woh + j; }
        *o = __floats2half2_rn(v.x, v.y);
    }
}

// ===========================================================================
// Fused prep 3: zero ONLY invisible token rows of the fp32 output.
// ===========================================================================
__global__ __launch_bounds__(256) void zero_inv(float4* __restrict__ out)
{
    const int CH = DIMC / 4;  // 512 float4 per row
    for (int i = blockIdx.x * 256 + threadIdx.x; i < BB * SS * (CH / 4); i += gridDim.x * 256) {
        const int row = i / (CH / 4);
        if (g_mask[row]) continue;
        const int c0 = (i % (CH / 4)) * 4;
        float4 z = make_float4(0.f, 0.f, 0.f, 0.f);
        float4* p = out + (size_t)row * CH + c0;
        p[0] = z; p[1] = z; p[2] = z; p[3] = z;
    }
}

// ===========================================================================
// FP16 mma.sync GEMM over COMPACTED visible rows.
// R15: register-level software pipelining (fragment double-buffer) + early
// cp.async prefetch, to lift tensor-pipe utilization from 44%.
// MODE 1 (gemm1): gathered A rows; fused RMSNorm+RoPE; fp16 compacted out.
// MODE 0 (gemm2): compacted A rows; fp32 epilogue scattered to token rows.
// ===========================================================================
#define HROW   72
#define HTILE  (128 * HROW)
#define HSTAGE (2 * HTILE)
#define HGEMM_SMEM (3 * HSTAGE * 2)      // 110592 B

template <int MODE>
__global__ __launch_bounds__(256, 2) void gemm_h(const __half* __restrict__ A,
                                                 const __half* __restrict__ Bm,
                                                 float* __restrict__ Cf,
                                                 __half* __restrict__ Ch,
                                                 const float* __restrict__ qw,
                                                 const float* __restrict__ kw,
                                                 const float* __restrict__ fcos,
                                                 const float* __restrict__ fsin,
                                                 const int* __restrict__ vidx,
                                                 const int* __restrict__ nvis,
                                                 int N, int K)
{
    const int b  = blockIdx.y >> 4;
    const int lt = blockIdx.y & 15;
    const int nv = nvis[b];
    if (lt * 128 >= nv) return;

    extern __shared__ __align__(16) char smc[];
    const uint32_t smb = smem_u32(smc);
    const int t = threadIdx.x;
    const int lane = t & 31;
    const int wid = t >> 5;
    const int wr = wid >> 2;
    const int wc = wid & 3;
    const int g = lane >> 2;
    const int q = lane & 3;
    const int n0 = blockIdx.x * 128;
    const int NK = K >> 6;
    const int m0l = lt * 128;
    const int* vidx_b = vidx + b * SS;

    const int cq = t & 7;
    const int r0 = t >> 3;
    const __half* aptr[4];
#pragma unroll
    for (int i = 0; i < 4; i++) {
        const int r = r0 + 32 * i;
        int j = m0l + r;
        if (MODE == 1) {
            if (j >= nv) j = nv - 1;
            aptr[i] = A + ((size_t)b * SS + vidx_b[j]) * K + cq * 8;
        } else {
            aptr[i] = A + ((size_t)b * SS + j) * K + cq * 8;
        }
    }
    const __half* gB = Bm + (size_t)n0 * K + cq * 8;

    float c[4][4][4];
#pragma unroll
    for (int i = 0; i < 4; i++)
#pragma unroll
        for (int j = 0; j < 4; j++)
#pragma unroll
            for (int r = 0; r < 4; r++) c[i][j][r] = 0.f;

#pragma unroll
    for (int s = 0; s < 2; s++) {
        const uint32_t sb = smb + s * HSTAGE * 2;
#pragma unroll
        for (int i = 0; i < 4; i++) {
            const int r = r0 + 32 * i;
            const uint32_t so = (uint32_t)(r * HROW + cq * 8) * 2u;
            cp16(sb + so, aptr[i] + s * 64);
            cp16(sb + HTILE * 2 + so, gB + (size_t)r * K + s * 64);
        }
        CP_COMMIT();
    }

    const uint32_t lrow = (uint32_t)(lane & 15);
    const uint32_t lhi  = (uint32_t)(lane >> 4) * 8u;

    for (int kt = 0; kt < NK; kt++) {
        CP_WAIT(1);
        __syncthreads();

        // Early prefetch of kt+2: give the memory pipe a head start; the
        // target buffer (kt+2)%3 was fully consumed in iteration kt-1 and the
        // barrier above ordered every warp past that point.
        const int pf = kt + 2;
        if (pf < NK) {
            const uint32_t sb = smb + (pf % 3) * HSTAGE * 2;
#pragma unroll
            for (int i = 0; i < 4; i++) {
                const int r = r0 + 32 * i;
                const uint32_t so = (uint32_t)(r * HROW + cq * 8) * 2u;
                cp16(sb + so, aptr[i] + pf * 64);
                cp16(sb + HTILE * 2 + so, gB + (size_t)r * K + pf * 64);
            }
        }
        CP_COMMIT();

        const uint32_t st = smb + (kt % 3) * HSTAGE * 2;
        const uint32_t aB = st + ((wr * 64 + lrow) * HROW + lhi) * 2;
        const uint32_t bB = st + HTILE * 2 + ((wc * 32 + lrow) * HROW + lhi) * 2;

        // Software-pipelined fragments: load ks=0, then overlap ks+1 loads
        // with the 16 MMAs of step ks.  af: 2x16 regs, bf: 2x8 regs.
        uint32_t af[2][4][4];
        uint32_t bf[2][4][2];
        {
            uint32_t rb[4];
            ldsm4(rb, bB);
            bf[0][0][0] = rb[0]; bf[0][1][0] = rb[1];
            bf[0][0][1] = rb[2]; bf[0][1][1] = rb[3];
            ldsm4(rb, bB + (uint32_t)(16 * HROW * 2));
            bf[0][2][0] = rb[0]; bf[0][3][0] = rb[1];
            bf[0][2][1] = rb[2]; bf[0][3][1] = rb[3];
#pragma unroll
            for (int i = 0; i < 4; i++)
                ldsm4(af[0][i], aB + (uint32_t)(i * 16 * HROW * 2));
        }

#pragma unroll
        for (int ks = 0; ks < 4; ks++) {
            const int cur = ks & 1;
            const int nxt = cur ^ 1;
            if (ks < 3) {
                const uint32_t ko = (uint32_t)((ks + 1) * 32);
                uint32_t rb[4];
                ldsm4(rb, bB + ko);
                bf[nxt][0][0] = rb[0]; bf[nxt][1][0] = rb[1];
                bf[nxt][0][1] = rb[2]; bf[nxt][1][1] = rb[3];
                ldsm4(rb, bB + (uint32_t)(16 * HROW * 2) + ko);
                bf[nxt][2][0] = rb[0]; bf[nxt][3][0] = rb[1];
                bf[nxt][2][1] = rb[2]; bf[nxt][3][1] = rb[3];
#pragma unroll
                for (int i = 0; i < 4; i++)
                    ldsm4(af[nxt][i], aB + (uint32_t)(i * 16 * HROW * 2) + ko);
            }
#pragma unroll
            for (int i = 0; i < 4; i++)
#pragma unroll
                for (int j = 0; j < 4; j++)
                    mma_f16(c[i][j], af[cur][i][0], af[cur][i][1],
                            af[cur][i][2], af[cur][i][3],
                            bf[cur][j][0], bf[cur][j][1]);
        }
    }

    if (MODE == 0) {
#pragma unroll
        for (int i = 0; i < 4; i++) {
#pragma unroll
            for (int rh = 0; rh < 2; rh++) {
                const int j = m0l + wr * 64 + i * 16 + rh * 8 + g;
                if (j >= nv) continue;
                const int tok = vidx_b[j];
                float* op = Cf + ((size_t)b * SS + tok) * N + n0;
#pragma unroll
                for (int jj = 0; jj < 4; jj++) {
                    const int col = wc * 32 + jj * 8 + q * 2;
                    *(float2*)(op + col) =
                        make_float2(c[i][jj][2 * rh], c[i][jj][2 * rh + 1]);
                }
            }
        }
        return;
    }

    // ---- MODE 1: fused per-head RMSNorm + RoPE, fp16 compacted out ----
    const int head = n0 >> 7;
    const int ht = (head < NH) ? 0 : ((head < NH + NKV) ? 1 : 2);
    const float* wv = (ht == 0) ? qw : kw;

    __syncthreads();
    float4* rsum = (float4*)smc;

#pragma unroll
    for (int i = 0; i < 4; i++) {
#pragma unroll
        for (int rh = 0; rh < 2; rh++) {
            float p = 0.f;
#pragma unroll
            for (int j = 0; j < 4; j++) {
                float v0 = c[i][j][2 * rh], v1 = c[i][j][2 * rh + 1];
                p += v0 * v0 + v1 * v1;
            }
            p += __shfl_xor_sync(0xffffffffu, p, 1);
            p += __shfl_xor_sync(0xffffffffu, p, 2);
            if (q == 0)
                ((float*)&rsum[wr * 64 + i * 16 + rh * 8 + g])[wc] = p;
        }
    }
    __syncthreads();

#pragma unroll
    for (int i = 0; i < 4; i++) {
#pragma unroll
        for (int rh = 0; rh < 2; rh++) {
            const int lr = wr * 64 + i * 16 + rh * 8 + g;
            float4 rs = rsum[lr];
            const float tot = rs.x + rs.y + rs.z + rs.w;
            const float rn = rsqrtf(tot * (1.f / HD) + EPSF);
            const int j = m0l + lr;
            const int jc = (j < nv) ? j : nv - 1;
            const int s = vidx_b[jc];
            __half* op = Ch + ((size_t)b * SS + j) * QKVC + n0;
#pragma unroll
            for (int jj = 0; jj < 4; jj++) {
                const int col = wc * 32 + jj * 8 + 2 * q;
                float v0 = c[i][jj][2 * rh], v1 = c[i][jj][2 * rh + 1];
                if (ht < 2) {
                    const float xn0 = v0 * rn * wv[col];
                    const float xn1 = v1 * rn * wv[col + 1];
                    const float cs = fcos[s * HD + col];
                    const float sn = fsin[s * HD + col];
                    v0 = xn0 * cs - xn1 * sn;
                    v1 = xn1 * cs + xn0 * sn;
                }
                *(__half2*)(op + col) = __floats2half2_rn(v0, v1);
            }
        }
    }
}

// ===========================================================================
// FP16 flash attention over COMPACTED rows (unchanged hot loop).
// ===========================================================================
#define AKROW 136
#define KTH   (64 * AKROW)
#define STH   (2 * KTH)
#define POH   (2 * STH)
#define PROW  72
#define SVB   ((POH + 128 * PROW) * 2)
#define ATTH_SMEM (SVB + 2 * 64 * 4 + 64)

__device__ __forceinline__ void ld_kv_c(uint32_t sb, const __half* KBbase, int tile, int t)
{
    const int c = t & 15;
    const int r0 = t >> 4;
#pragma unroll
    for (int i = 0; i < 4; i++) {
        const int r = r0 + 16 * i;
        const __half* Kg = KBbase + (size_t)(tile * 64 + r) * QKVC;
        const uint32_t so = (uint32_t)(r * AKROW + c * 8) * 2u;
        cp16(sb + so, Kg + c * 8);
        cp16(sb + KTH * 2 + so, Kg + NKV * HD + c * 8);
    }
}

__global__ __launch_bounds__(256, 1) void attn_h(const __half* __restrict__ qkvh,
                                                 const int* __restrict__ nvis,
                                                 __half* __restrict__ outp)
{
    const int qt = blockIdx.x;
    const int b  = blockIdx.z;
    const int nv = nvis[b];
    const int ntile = (nv + 63) >> 6;
    if (qt >= ntile) return;

    extern __shared__ __align__(16) char smc[];
    __half* hsm = (__half*)smc;
    const uint32_t smb = smem_u32(smc);
    const int t = threadIdx.x;
    const int lane = t & 31;
    const int w = t >> 5;
    const int g = lane >> 2;
    const int q = lane & 3;
    const int hp = blockIdx.y;
    const int h  = hp * 2 + (w >> 2);
    const int kvh = hp >> 1;
    const int qrow = (w & 3) << 4;

    const size_t tokbase = (size_t)b * SS;

    const int j0 = qt * 64 + qrow + g;
    const int j1 = j0 + 8;
    const int jc0 = (j0 < nv) ? j0 : nv - 1;
    const int jc1 = (j1 < nv) ? j1 : nv - 1;
    const __half* Qg0 = qkvh + (tokbase + jc0) * QKVC + h * HD;
    const __half* Qg1 = qkvh + (tokbase + jc1) * QKVC + h * HD;
    uint32_t qf[8][4];
#pragma unroll
    for (int kc = 0; kc < 8; kc++) {
        qf[kc][0] = *(const uint32_t*)(Qg0 + kc * 16 + 2 * q);
        qf[kc][1] = *(const uint32_t*)(Qg1 + kc * 16 + 2 * q);
        qf[kc][2] = *(const uint32_t*)(Qg0 + kc * 16 + 8 + 2 * q);
        qf[kc][3] = *(const uint32_t*)(Qg1 + kc * 16 + 8 + 2 * q);
    }

    __half* pwarp = hsm + POH + (16 * w) * PROW;
    float* svb = (float*)(smc + SVB);

    float o[16][4];
#pragma unroll
    for (int nf = 0; nf < 16; nf++)
#pragma unroll
        for (int r = 0; r < 4; r++) o[nf][r] = 0.f;
    float m0p = -INFINITY, m1p = -INFINITY, l0 = 0.f, l1 = 0.f;
    const float scale = 0.08838834764831843f;

    const __half* KBbase = qkvh + tokbase * QKVC + DIMC + kvh * HD;

#pragma unroll
    for (int s = 0; s < 2; s++) {
        if (s < ntile) {
            ld_kv_c(smb + s * STH * 2, KBbase, s, t);
            if (t < 64) svb[s * 64 + t] = (s * 64 + t < nv) ? 0.f : NEGF;
        }
        CP_COMMIT();
    }

    const uint32_t lrow = (uint32_t)(lane & 15);
    const uint32_t lhi  = (uint32_t)(lane >> 4) * 8u;

    for (int kt = 0; kt < ntile; kt++) {
        CP_WAIT(1);
        __syncthreads();

        const uint32_t ksb = smb + (kt & 1) * STH * 2;
        const uint32_t vsb = ksb + KTH * 2;
        const float* svp = svb + (kt & 1) * 64;

        float c8[8][4];
#pragma unroll
        for (int f = 0; f < 8; f++)
#pragma unroll
            for (int r = 0; r < 4; r++) c8[f][r] = 0.f;

        const uint32_t kfB = ksb + (lrow * AKROW + lhi) * 2;
#pragma unroll
        for (int kc = 0; kc < 8; kc++) {
#pragma unroll
            for (int fb = 0; fb < 4; fb++) {
                uint32_t r[4];
                ldsm4(r, kfB + (uint32_t)(fb * 16 * AKROW * 2 + kc * 32));
                mma_f16(c8[2 * fb],     qf[kc][0], qf[kc][1], qf[kc][2], qf[kc][3], r[0], r[2]);
                mma_f16(c8[2 * fb + 1], qf[kc][0], qf[kc][1], qf[kc][2], qf[kc][3], r[1], r[3]);
            }
        }

        float rmx0 = -INFINITY, rmx1 = -INFINITY;
#pragma unroll
        for (int f = 0; f < 8; f++) {
            float a0 = svp[8 * f + 2 * q], a1 = svp[8 * f + 2 * q + 1];
            c8[f][0] = c8[f][0] * scale + a0;
            c8[f][1] = c8[f][1] * scale + a1;
            c8[f][2] = c8[f][2] * scale + a0;
            c8[f][3] = c8[f][3] * scale + a1;
            rmx0 = fmaxf(rmx0, fmaxf(c8[f][0], c8[f][1]));
            rmx1 = fmaxf(rmx1, fmaxf(c8[f][2], c8[f][3]));
        }
        rmx0 = fmaxf(rmx0, __shfl_xor_sync(0xffffffffu, rmx0, 1));
        rmx0 = fmaxf(rmx0, __shfl_xor_sync(0xffffffffu, rmx0, 2));
        rmx1 = fmaxf(rmx1, __shfl_xor_sync(0xffffffffu, rmx1, 1));
        rmx1 = fmaxf(rmx1, __shfl_xor_sync(0xffffffffu, rmx1, 2));

        float mn0 = fmaxf(m0p, rmx0), mn1 = fmaxf(m1p, rmx1);
        float al0 = __expf(m0p - mn0), al1 = __expf(m1p - mn1);
        m0p = mn0; m1p = mn1;

        float ps0 = 0.f, ps1 = 0.f;
#pragma unroll
        for (int f = 0; f < 8; f++) {
            float p0 = __expf(c8[f][0] - mn0);
            float p1 = __expf(c8[f][1] - mn0);
            float p2 = __expf(c8[f][2] - mn1);
            float p3 = __expf(c8[f][3] - mn1);
            ps0 += p0 + p1; ps1 += p2 + p3;
            *(__half2*)(pwarp + g * PROW + f * 8 + 2 * q) = __floats2half2_rn(p0, p1);
            *(__half2*)(pwarp + (g + 8) * PROW + f * 8 + 2 * q) = __floats2half2_rn(p2, p3);
        }
        ps0 += __shfl_xor_sync(0xffffffffu, ps0, 1);
        ps0 += __shfl_xor_sync(0xffffffffu, ps0, 2);
        ps1 += __shfl_xor_sync(0xffffffffu, ps1, 1);
        ps1 += __shfl_xor_sync(0xffffffffu, ps1, 2);
        l0 = l0 * al0 + ps0;
        l1 = l1 * al1 + ps1;

#pragma unroll
        for (int nf = 0; nf < 16; nf++) {
            o[nf][0] *= al0; o[nf][1] *= al0;
            o[nf][2] *= al1; o[nf][3] *= al1;
        }
        __syncwarp();

        const uint32_t vfB = vsb + (lrow * AKROW + lhi) * 2;
#pragma unroll
        for (int kc = 0; kc < 4; kc++) {
            uint32_t a0 = *(const uint32_t*)(pwarp + g * PROW + kc * 16 + 2 * q);
            uint32_t a1 = *(const uint32_t*)(pwarp + (g + 8) * PROW + kc * 16 + 2 * q);
            uint32_t a2 = *(const uint32_t*)(pwarp + g * PROW + kc * 16 + 8 + 2 * q);
            uint32_t a3 = *(const uint32_t*)(pwarp + (g + 8) * PROW + kc * 16 + 8 + 2 * q);
#pragma unroll
            for (int db = 0; db < 8; db++) {
                uint32_t r[4];
                ldsm4t(r, vfB + (uint32_t)(kc * 16 * AKROW * 2 + db * 32));
                mma_f16(o[2 * db],     a0, a1, a2, a3, r[0], r[1]);
                mma_f16(o[2 * db + 1], a0, a1, a2, a3, r[2], r[3]);
            }
        }

        __syncthreads();
        const int pf = kt + 2;
        if (pf < ntile) {
            ld_kv_c(smb + (pf & 1) * STH * 2, KBbase, pf, t);
            if (t < 64) svb[(pf & 1) * 64 + t] = (pf * 64 + t < nv) ? 0.f : NEGF;
        }
        CP_COMMIT();
    }

    if (j0 < nv) {
        const float f0 = 1.f / l0;
        __half* o0 = outp + (tokbase + j0) * DIMC + h * HD;
#pragma unroll
        for (int nf = 0; nf < 16; nf++)
            *(__half2*)(o0 + nf * 8 + 2 * q) = __floats2half2_rn(o[nf][0] * f0, o[nf][1] * f0);
    }
    if (j1 < nv) {
        const float f1 = 1.f / l1;
        __half* o1 = outp + (tokbase + j1) * DIMC + h * HD;
#pragma unroll
        for (int nf = 0; nf < 16; nf++)
            *(__half2*)(o1 + nf * 8 + 2 * q) = __floats2half2_rn(o[nf][2] * f1, o[nf][3] * f1);
    }
}

// ---------------------------------------------------------------------------
extern "C" void kernel_launch(void* const* d_in, const int* in_sizes, int n_in,
                              void* d_out, int out_size)
{
    const float* x    = (const float*)d_in[0];
    const float* wqkv = (const float*)d_in[1];
    const float* wo   = (const float*)d_in[2];
    const float* qw   = (const float*)d_in[3];
    const float* kw   = (const float*)d_in[4];
    const float* fc   = (const float*)d_in[5];
    const float* fs   = (const float*)d_in[6];
    const unsigned char* visraw = (const unsigned char*)d_in[7];
    float* out = (float*)d_out;

    __half *qkvh, *attnh, *xh, *wqh, *woh;
    int *vidx, *nvis;
    cudaGetSymbolAddress((void**)&qkvh, g_qkvh);
    cudaGetSymbolAddress((void**)&attnh, g_attnh);
    cudaGetSymbolAddress((void**)&xh, g_xh);
    cudaGetSymbolAddress((void**)&wqh, g_wqh);
    cudaGetSymbolAddress((void**)&woh, g_woh);
    cudaGetSymbolAddress((void**)&vidx, g_vidx);
    cudaGetSymbolAddress((void**)&nvis, g_nvis);

    // 0) Prep: mask canonicalize+compact; fused fp16 conversions; masked zero
    prep_mask<<<BB, 1024>>>(visraw);
    cvt_all<<<2048, 256>>>((const float2*)x, (const float2*)wqkv, (const float2*)wo,
                           (__half2*)xh, (__half2*)wqh, (__half2*)woh);
    zero_inv<<<1024, 256>>>((float4*)out);

    // 1) QKV projection over visible rows + fused RMSNorm/RoPE -> compacted qkvh
    cudaFuncSetAttribute(gemm_h<1>, cudaFuncAttributeMaxDynamicSharedMemorySize, HGEMM_SMEM);
    gemm_h<1><<<dim3(QKVC / 128, BB * 16), 256, HGEMM_SMEM>>>(
        xh, wqh, nullptr, qkvh, qw, kw, fc, fs, vidx, nvis, QKVC, DIMC);

    // 2) Attention over compacted rows -> compacted attnh
    cudaFuncSetAttribute(attn_h, cudaFuncAttributeMaxDynamicSharedMemorySize, ATTH_SMEM);
    attn_h<<<dim3(SS / 64, NH / 2, BB), 256, ATTH_SMEM>>>(qkvh, nvis, attnh);

    // 3) Output projection over visible rows -> scattered fp32 out
    cudaFuncSetAttribute(gemm_h<0>, cudaFuncAttributeMaxDynamicSharedMemorySize, HGEMM_SMEM);
    gemm_h<0><<<dim3(DIMC / 128, BB * 16), 256, HGEMM_SMEM>>>(
        attnh, woh, out, nullptr, nullptr, nullptr, nullptr, nullptr,
        vidx, nvis, DIMC, DIMC);
}